// round 14
// baseline (speedup 1.0000x reference)
#include <cuda_runtime.h>
#include <cuda_bf16.h>
#include <cstdint>

// Problem constants (H=W=256, SMALL=8, LARGE=16, B=2)
#define HW      65536
#define NB      2
#define WNUM    1024
#define S2      64
#define L2      256
#define NTILE   (WNUM*NB)     // 2048
#define NBLK    592           // = 148 SMs * 4 blocks, exact single wave
#define NCORRB  128           // corr blocks: 8 warps * 2 tiles = 16 tiles each
#define K1      24            // bulk iters for corr blocks   (mult of 8)
#define K2      64            // bulk iters for plain blocks  (mult of 8)
// 128*256*24 + 464*256*64 = 786432 + 7602176 = 8388608 float4 = all of P
#define CORR_REGION (NCORRB * 256 * K1)   // 786432

__device__ int    g_partner[NB * HW];   // 512 KB (L2-resident)
__device__ float  g_corrR[NTILE];       // per-tile nll_sum/c_num
__device__ float  g_bulk[NBLK];
__device__ int    g_sync1;              // scatter barrier (zero-init, rearmed)
__device__ int    g_ticket;             // completion ticket (zero-init, rearmed)

__device__ __forceinline__ float warp_sum(float v) {
    #pragma unroll
    for (int o = 16; o > 0; o >>= 1) v += __shfl_down_sync(0xFFFFFFFFu, v, o);
    return v;
}

// 8-deep explicit load batch: forces 8 LDG.128 in flight per warp.
__device__ __forceinline__ void batch8(const float4* __restrict__ p, int stride,
                                       float& a0, float& a1) {
    float4 v[8];
    #pragma unroll
    for (int i = 0; i < 8; i++) v[i] = __ldcs(p + i * stride);
    #pragma unroll
    for (int i = 0; i < 8; i++) { a0 += v[i].x + v[i].y; a1 += v[i].z + v[i].w; }
}

// ---------------------------------------------------------------------------
// Single fused kernel; 592 blocks = exactly 4 per SM (occ 4, <=64 regs for
// deep load batching).
//  corr blocks (0..127): scatter 1024 entries -> K1 bulk iters -> barrier
//    (drained) -> 2 tiles per warp corrections -> done (exit early; BW stays
//    saturated by the 464 plain blocks)
//  plain blocks (128..591): K2 bulk iters, zero preamble
// ---------------------------------------------------------------------------
__global__ __launch_bounds__(256, 4)
void k_all(const float4* __restrict__ P4,
           const float*  __restrict__ Pf,
           const int*    __restrict__ index_r,
           const int*    __restrict__ lw_abs,
           float*        __restrict__ out) {
    const int bid  = blockIdx.x;
    const int tid  = threadIdx.x;
    const int lane = tid & 31;
    const int wrp  = tid >> 5;

    float a0 = 0.f, a1 = 0.f;          // bulk accumulators

    if (bid < NCORRB) {
        // ---- scatter slice: 1024 entries (4/thread), coalesced reads ----
        #pragma unroll
        for (int r = 0; r < 4; r++) {
            int e    = bid * 1024 + r * 256 + tid;     // covers NB*HW exactly
            int b    = e >> 16;
            int j    = e & (HW - 1);
            int idx0 = index_r[(b * 2 + 0) * HW + j];
            int idx1 = index_r[(b * 2 + 1) * HW + j];
            g_partner[b * HW + idx1] = idx0;
        }
        __threadfence();
        __syncthreads();
        if (tid == 0) atomicAdd(&g_sync1, 1);   // arrive early, wait later

        // ---- bulk share (hides all scatters) ----
        const int base = bid * 256 + tid;       // region [0, CORR_REGION)
        #pragma unroll
        for (int k = 0; k < K1 / 8; k++) {
            batch8(P4 + base + k * 8 * (NCORRB * 256), NCORRB * 256, a0, a1);
        }

        // ---- barrier wait (long drained) ----
        if (tid == 0) {
            while (*((volatile int*)&g_sync1) < NCORRB) { }
        }
        __syncthreads();
        __threadfence();

        // ---- per-warp corrections: 2 tiles per warp ----
        #pragma unroll
        for (int t = 0; t < 2; t++) {
            const int tile = (bid * 8 + wrp) * 2 + t;    // tile = w*2 + b
            const int w    = tile >> 1;
            const int b    = tile & 1;
            const int r0   = (w >> 5) << 3;
            const int c0   = (w & 31) << 3;
            const float* Pt = Pf + (size_t)tile * (S2 * L2);

            float absd = 0.f, nll = 0.f;
            int   cnt  = 0;
            #pragma unroll
            for (int k = 0; k < 8; k++) {
                int l  = lane + 32 * k;
                int lw = __ldg(lw_abs + w * L2 + l);
                int v  = g_partner[b * HW + lw];             // plw
                int i  = (v >> 8) - r0;
                int j  = (v & 255) - c0;
                if ((unsigned)i < 8u && (unsigned)j < 8u && !(v == 0 && lw == 0)) {
                    float p = __ldg(Pt + (i * 8 + j) * L2 + l);
                    absd += 1.f - 2.f * p;                   // |p-1| - p
                    nll  -= __logf(fminf(fmaxf(p, 1e-6f), 1.f - 1e-6f));
                    cnt++;
                }
            }
            float cntf = (float)cnt;
            absd = warp_sum(absd);
            nll  = warp_sum(nll);
            cntf = warp_sum(cntf);
            if (lane == 0) {
                g_corrR[tile] = nll / cntf;
                a1 += absd;            // fold absd corr into bulk partial once
            }
        }
    } else {
        // ---- plain block: bulk only, zero preamble ----
        const int base = CORR_REGION + (bid - NCORRB) * 256 + tid;
        #pragma unroll
        for (int k = 0; k < K2 / 8; k++) {
            batch8(P4 + base + k * 8 * ((NBLK - NCORRB) * 256),
                   (NBLK - NCORRB) * 256, a0, a1);
        }
    }
    float acc = a0 + a1;

    // ---- block reduction -> g_bulk, ticket ----
    acc = warp_sum(acc);
    __shared__ float red[8];
    __shared__ bool  s_last;
    if (lane == 0) red[wrp] = acc;
    __syncthreads();
    if (wrp == 0) {
        float a = (lane < 8) ? red[lane] : 0.f;
        #pragma unroll
        for (int o = 4; o > 0; o >>= 1) a += __shfl_down_sync(0xFFFFFFFFu, a, o);
        if (lane == 0) {
            g_bulk[bid] = a;
            __threadfence();
            int t = atomicAdd(&g_ticket, 1);
            s_last = (t == NBLK - 1);
        }
    }
    __syncthreads();

    // ---- final fixed-order combine (deterministic) ----
    if (s_last) {
        float sumP = 0.f, sumR = 0.f;
        for (int i = tid; i < NBLK; i += 256) sumP += g_bulk[i];
        for (int i = tid; i < NTILE; i += 256) sumR += g_corrR[i];
        sumP = warp_sum(sumP);
        sumR = warp_sum(sumR);
        __shared__ float sp[8], sr[8];
        if (lane == 0) { sp[wrp] = sumP; sr[wrp] = sumR; }
        __syncthreads();
        if (wrp == 0) {
            float p = (lane < 8) ? sp[lane] : 0.f;
            float r = (lane < 8) ? sr[lane] : 0.f;
            #pragma unroll
            for (int o = 4; o > 0; o >>= 1) {
                p += __shfl_down_sync(0xFFFFFFFFu, p, o);
                r += __shfl_down_sync(0xFFFFFFFFu, r, o);
            }
            if (lane == 0) {
                out[0] = r / (float)NTILE;                        // l_cm
                out[1] = p / (float)((size_t)NTILE * S2 * L2);    // l_c
                g_ticket = 0;                                     // rearm
                g_sync1  = 0;
            }
        }
    }
}

// ---------------------------------------------------------------------------
// Launch.  Inputs: [0] P f32, [1] index_r i32, [2] sw_abs i32, [3] lw_abs i32.
// ---------------------------------------------------------------------------
extern "C" void kernel_launch(void* const* d_in, const int* in_sizes, int n_in,
                              void* d_out, int out_size) {
    const float4* P4     = (const float4*)d_in[0];
    const float*  Pf     = (const float*)d_in[0];
    const int*    idxr   = (const int*)d_in[1];
    const int*    lw_abs = (const int*)d_in[3];
    float*        out    = (float*)d_out;

    k_all<<<NBLK, 256>>>(P4, Pf, idxr, lw_abs, out);
}

// round 15
// speedup vs baseline: 1.1279x; 1.1279x over previous
#include <cuda_runtime.h>
#include <cuda_bf16.h>
#include <cstdint>

// Problem constants (H=W=256, SMALL=8, LARGE=16, B=2)
#define HW      65536
#define NB      2
#define WNUM    1024
#define S2      64
#define L2      256
#define NTILE   (WNUM*NB)     // 2048
#define NBLK    1024          // single wave at occ 7 (148*7 = 1036)
#define NCORRB  256           // blocks that also do scatter+corr
#define K1      20            // bulk iters for corr blocks  (R6 split: best measured)
#define K2      36            // bulk iters for plain blocks
// 256*256*20 + 768*256*36 = 1310720 + 7077888 = 8388608 float4 = all of P
#define CORR_REGION (NCORRB * 256 * K1)   // 1310720
#define DEPTH   4             // cp.async pipeline depth

__device__ int    g_partner[NB * HW];   // 512 KB (L2-resident)
__device__ float2 g_corr[NTILE];        // {nll_sum/c_num, absd_correction}
__device__ float  g_bulk[NBLK];
__device__ int    g_sync1;              // scatter barrier (zero-init, rearmed)
__device__ int    g_ticket;             // completion ticket (zero-init, rearmed)

__device__ __forceinline__ float warp_sum(float v) {
    #pragma unroll
    for (int o = 16; o > 0; o >>= 1) v += __shfl_down_sync(0xFFFFFFFFu, v, o);
    return v;
}

// ---- cp.async helpers (16B, .cg = L2-only, bypass L1) ----
__device__ __forceinline__ void cp16(uint32_t saddr, const void* gptr) {
    asm volatile("cp.async.cg.shared.global [%0], [%1], 16;"
                 :: "r"(saddr), "l"(gptr));
}
__device__ __forceinline__ void cp_commit() {
    asm volatile("cp.async.commit_group;");
}
template<int N> __device__ __forceinline__ void cp_wait() {
    asm volatile("cp.async.wait_group %0;" :: "n"(N));
}

// Depth-4 cp.async pipelined bulk sum. Each thread owns 4 private 16B slots;
// no cross-thread smem deps -> no __syncthreads in the loop. The async-copy
// engine carries the outstanding requests (not registers / LDG scoreboard).
template<int K>
__device__ __forceinline__ void bulk_stream(const float4* __restrict__ src,
                                            int stride4, float4* buf, int tid,
                                            float& a0, float& a1) {
    uint32_t sbase = (uint32_t)__cvta_generic_to_shared(buf + tid);
    // prologue: issue DEPTH-1 tiles, one group each
    #pragma unroll
    for (int s = 0; s < DEPTH - 1; s++) {
        cp16(sbase + s * (256 * 16), src + (size_t)s * stride4);
        cp_commit();
    }
    #pragma unroll 4
    for (int k = 0; k < K; k++) {
        if (k + DEPTH - 1 < K) {
            cp16(sbase + ((k + DEPTH - 1) % DEPTH) * (256 * 16),
                 src + (size_t)(k + DEPTH - 1) * stride4);
        }
        cp_commit();                    // exactly one group per iter
        cp_wait<DEPTH - 1>();           // groups 0..k complete -> tile k ready
        float4 p = buf[(k % DEPTH) * 256 + tid];
        a0 += p.x + p.y;
        a1 += p.z + p.w;
    }
    cp_wait<0>();                       // drain before smem reuse elsewhere
}

// ---------------------------------------------------------------------------
// Single fused kernel, single wave — R6 geometry, cp.async load path.
//  corr blocks (0..255): scatter -> K1 bulk -> barrier (drained) -> corr
//  plain blocks (256..1023): K2 bulk, zero preamble, never wait
// ---------------------------------------------------------------------------
__global__ __launch_bounds__(256, 7)
void k_all(const float4* __restrict__ P4,
           const float*  __restrict__ Pf,
           const int*    __restrict__ index_r,
           const int*    __restrict__ lw_abs,
           float*        __restrict__ out) {
    const int bid  = blockIdx.x;
    const int tid  = threadIdx.x;
    const int lane = tid & 31;
    const int wrp  = tid >> 5;

    __shared__ float4 buf[DEPTH * 256];       // 16 KB: per-thread private slots

    float a0 = 0.f, a1 = 0.f;

    if (bid < NCORRB) {
        // ---- scatter slice: 512 entries, coalesced reads ----
        #pragma unroll
        for (int r = 0; r < 2; r++) {
            int e    = bid * 512 + r * 256 + tid;      // covers NB*HW exactly
            int b    = e >> 16;
            int j    = e & (HW - 1);
            int idx0 = index_r[(b * 2 + 0) * HW + j];
            int idx1 = index_r[(b * 2 + 1) * HW + j];
            g_partner[b * HW + idx1] = idx0;
        }
        __threadfence();
        __syncthreads();
        if (tid == 0) atomicAdd(&g_sync1, 1);   // arrive early, wait later

        // ---- bulk share (hides all scatters) ----
        bulk_stream<K1>(P4 + bid * 256 + tid, NCORRB * 256, buf, tid, a0, a1);

        // ---- barrier wait (long drained) ----
        if (tid == 0) {
            while (*((volatile int*)&g_sync1) < NCORRB) { }
        }
        __syncthreads();
        __threadfence();

        // ---- per-warp tile corrections (tile = bid*8 + warp) ----
        const int tile = bid * 8 + wrp;
        const int w    = tile >> 1;
        const int b    = tile & 1;
        const int r0   = (w >> 5) << 3;
        const int c0   = (w & 31) << 3;
        const float* Pt = Pf + (size_t)tile * (S2 * L2);

        float absd = 0.f, nll = 0.f;
        int   cnt  = 0;
        #pragma unroll
        for (int k = 0; k < 8; k++) {
            int l  = lane + 32 * k;
            int lw = __ldg(lw_abs + w * L2 + l);
            int v  = g_partner[b * HW + lw];             // plw
            int i  = (v >> 8) - r0;
            int j  = (v & 255) - c0;
            if ((unsigned)i < 8u && (unsigned)j < 8u && !(v == 0 && lw == 0)) {
                float p = __ldg(Pt + (i * 8 + j) * L2 + l);
                absd += 1.f - 2.f * p;                   // |p-1| - p
                nll  -= __logf(fminf(fmaxf(p, 1e-6f), 1.f - 1e-6f));
                cnt++;
            }
        }
        float cntf = (float)cnt;
        absd = warp_sum(absd);
        nll  = warp_sum(nll);
        cntf = warp_sum(cntf);
        if (lane == 0) g_corr[tile] = make_float2(nll / cntf, absd);
    } else {
        // ---- plain block: bulk only, zero preamble ----
        bulk_stream<K2>(P4 + CORR_REGION + (bid - NCORRB) * 256 + tid,
                        (NBLK - NCORRB) * 256, buf, tid, a0, a1);
    }
    float acc = a0 + a1;

    // ---- block reduction -> g_bulk, ticket ----
    acc = warp_sum(acc);
    __shared__ float red[8];
    __shared__ bool  s_last;
    if (lane == 0) red[wrp] = acc;
    __syncthreads();
    if (wrp == 0) {
        float a = (lane < 8) ? red[lane] : 0.f;
        #pragma unroll
        for (int o = 4; o > 0; o >>= 1) a += __shfl_down_sync(0xFFFFFFFFu, a, o);
        if (lane == 0) {
            g_bulk[bid] = a;
            __threadfence();
            int t = atomicAdd(&g_ticket, 1);
            s_last = (t == NBLK - 1);
        }
    }
    __syncthreads();

    // ---- final fixed-order combine (deterministic) ----
    if (s_last) {
        float sumP = 0.f, sumC = 0.f, sumR = 0.f;
        #pragma unroll
        for (int i = tid; i < NBLK; i += 256) sumP += g_bulk[i];
        #pragma unroll
        for (int i = tid; i < NTILE; i += 256) {
            float2 v = g_corr[i];
            sumR += v.x;
            sumC += v.y;
        }
        sumP = warp_sum(sumP);
        sumC = warp_sum(sumC);
        sumR = warp_sum(sumR);
        __shared__ float sp[8], sc[8], sr[8];
        if (lane == 0) { sp[wrp] = sumP; sc[wrp] = sumC; sr[wrp] = sumR; }
        __syncthreads();
        if (wrp == 0) {
            float p = (lane < 8) ? sp[lane] : 0.f;
            float c = (lane < 8) ? sc[lane] : 0.f;
            float r = (lane < 8) ? sr[lane] : 0.f;
            #pragma unroll
            for (int o = 4; o > 0; o >>= 1) {
                p += __shfl_down_sync(0xFFFFFFFFu, p, o);
                c += __shfl_down_sync(0xFFFFFFFFu, c, o);
                r += __shfl_down_sync(0xFFFFFFFFu, r, o);
            }
            if (lane == 0) {
                out[0] = r / (float)NTILE;                            // l_cm
                out[1] = (p + c) / (float)((size_t)NTILE * S2 * L2);  // l_c
                g_ticket = 0;                                         // rearm
                g_sync1  = 0;
            }
        }
    }
}

// ---------------------------------------------------------------------------
// Launch.  Inputs: [0] P f32, [1] index_r i32, [2] sw_abs i32, [3] lw_abs i32.
// ---------------------------------------------------------------------------
extern "C" void kernel_launch(void* const* d_in, const int* in_sizes, int n_in,
                              void* d_out, int out_size) {
    const float4* P4     = (const float4*)d_in[0];
    const float*  Pf     = (const float*)d_in[0];
    const int*    idxr   = (const int*)d_in[1];
    const int*    lw_abs = (const int*)d_in[3];
    float*        out    = (float*)d_out;

    k_all<<<NBLK, 256>>>(P4, Pf, idxr, lw_abs, out);
}

// round 16
// speedup vs baseline: 1.2193x; 1.0810x over previous
#include <cuda_runtime.h>
#include <cuda_bf16.h>
#include <cstdint>

// Problem constants (H=W=256, SMALL=8, LARGE=16, B=2)
#define HW      65536
#define NB      2
#define WNUM    1024
#define S2      64
#define L2      256
#define NTILE   (WNUM*NB)     // 2048
#define NBLK    1024          // single wave at occ 7 (148*7 = 1036)
#define NCORRB  256           // blocks that also do scatter+corr
#define K1      20            // bulk iters for corr blocks (R6 split)
#define K2      36            // bulk iters for plain blocks
// 256*256*20 + 768*256*36 = 1310720 + 7077888 = 8388608 float4 = all of P
#define CORR_REGION (NCORRB * 256 * K1)   // 1310720

__device__ int    g_partner[NB * HW];   // 512 KB (L2-resident)
__device__ float2 g_corr[NTILE];        // {nll_sum/c_num, absd_correction}
__device__ float  g_bulk[NBLK];
__device__ int    g_sync1;              // scatter barrier (zero-init, rearmed)
__device__ int    g_ticket;             // completion ticket (zero-init, rearmed)

__device__ __forceinline__ float warp_sum(float v) {
    #pragma unroll
    for (int o = 16; o > 0; o >>= 1) v += __shfl_down_sync(0xFFFFFFFFu, v, o);
    return v;
}

// ---------------------------------------------------------------------------
// R6 structure, single changed variable: CONTIGUOUS per-block bulk regions.
// Each block streams one dense region (seq 4KB steps) instead of 4MB strides
// -> DRAM row-buffer / channel locality.
//  corr blocks (0..255): scatter -> K1 bulk iters -> barrier (drained) ->
//    per-warp tile corrections (8 tiles/block)
//  plain blocks (256..1023): K2 bulk iters, zero preamble, never wait
// ---------------------------------------------------------------------------
__global__ __launch_bounds__(256, 7)
void k_all(const float4* __restrict__ P4,
           const float*  __restrict__ Pf,
           const int*    __restrict__ index_r,
           const int*    __restrict__ lw_abs,
           float*        __restrict__ out) {
    const int bid  = blockIdx.x;
    const int tid  = threadIdx.x;
    const int lane = tid & 31;
    const int wrp  = tid >> 5;

    float a0 = 0.f, a1 = 0.f;          // bulk accumulators
    float absd = 0.f, nll = 0.f;       // correction accumulators
    float cntf = 0.f;

    if (bid < NCORRB) {
        // ---- scatter slice: 512 entries, coalesced reads, random 4B stores ----
        #pragma unroll
        for (int r = 0; r < 2; r++) {
            int e    = bid * 512 + r * 256 + tid;      // 0..131071
            int b    = e >> 16;
            int j    = e & (HW - 1);
            int idx0 = index_r[(b * 2 + 0) * HW + j];
            int idx1 = index_r[(b * 2 + 1) * HW + j];
            g_partner[b * HW + idx1] = idx0;
        }
        __threadfence();
        __syncthreads();
        if (tid == 0) atomicAdd(&g_sync1, 1);   // arrive early, wait later

        // ---- bulk share: CONTIGUOUS region [bid*5120, bid*5120+5120) ----
        const int base = bid * (K1 * 256) + tid;
        #pragma unroll 4
        for (int k = 0; k < K1; k++) {
            float4 p = __ldcs(P4 + base + k * 256);
            a0 += p.x + p.y;
            a1 += p.z + p.w;
        }

        // ---- barrier wait (should already be drained) ----
        if (tid == 0) {
            while (*((volatile int*)&g_sync1) < NCORRB) { }
        }
        __syncthreads();
        __threadfence();

        // ---- per-warp tile corrections (tile = bid*8 + warp) ----
        const int tile = bid * 8 + wrp;
        const int w    = tile >> 1;
        const int b    = tile & 1;
        const int r0   = (w >> 5) << 3;
        const int c0   = (w & 31) << 3;
        const float* Pt = Pf + (size_t)tile * (S2 * L2);

        int cnt = 0;
        #pragma unroll
        for (int k = 0; k < 8; k++) {
            int l  = lane + 32 * k;
            int lw = __ldg(lw_abs + w * L2 + l);
            int v  = g_partner[b * HW + lw];             // plw
            int i  = (v >> 8) - r0;
            int j  = (v & 255) - c0;
            if ((unsigned)i < 8u && (unsigned)j < 8u && !(v == 0 && lw == 0)) {
                float p = __ldg(Pt + (i * 8 + j) * L2 + l);
                absd += 1.f - 2.f * p;                   // |p-1| - p
                nll  -= __logf(fminf(fmaxf(p, 1e-6f), 1.f - 1e-6f));
                cnt++;
            }
        }
        cntf = (float)cnt;
        absd = warp_sum(absd);
        nll  = warp_sum(nll);
        cntf = warp_sum(cntf);
        if (lane == 0) g_corr[tile] = make_float2(nll / cntf, absd);
    } else {
        // ---- plain block: CONTIGUOUS region after CORR_REGION ----
        const int base = CORR_REGION + (bid - NCORRB) * (K2 * 256) + tid;
        #pragma unroll 4
        for (int k = 0; k < K2; k++) {
            float4 p = __ldcs(P4 + base + k * 256);
            a0 += p.x + p.y;
            a1 += p.z + p.w;
        }
    }
    float acc = a0 + a1;

    // ---- block reduction -> g_bulk, ticket ----
    acc = warp_sum(acc);
    __shared__ float red[8];
    __shared__ bool  s_last;
    if (lane == 0) red[wrp] = acc;
    __syncthreads();
    if (wrp == 0) {
        float a = (lane < 8) ? red[lane] : 0.f;
        #pragma unroll
        for (int o = 4; o > 0; o >>= 1) a += __shfl_down_sync(0xFFFFFFFFu, a, o);
        if (lane == 0) {
            g_bulk[bid] = a;
            __threadfence();
            int t = atomicAdd(&g_ticket, 1);
            s_last = (t == NBLK - 1);
        }
    }
    __syncthreads();

    // ---- final fixed-order combine (deterministic) ----
    if (s_last) {
        float sumP = 0.f, sumC = 0.f, sumR = 0.f;
        #pragma unroll
        for (int i = tid; i < NBLK; i += 256) sumP += g_bulk[i];
        #pragma unroll
        for (int i = tid; i < NTILE; i += 256) {
            float2 v = g_corr[i];
            sumR += v.x;
            sumC += v.y;
        }
        sumP = warp_sum(sumP);
        sumC = warp_sum(sumC);
        sumR = warp_sum(sumR);
        __shared__ float sp[8], sc[8], sr[8];
        if (lane == 0) { sp[wrp] = sumP; sc[wrp] = sumC; sr[wrp] = sumR; }
        __syncthreads();
        if (wrp == 0) {
            float p = (lane < 8) ? sp[lane] : 0.f;
            float c = (lane < 8) ? sc[lane] : 0.f;
            float r = (lane < 8) ? sr[lane] : 0.f;
            #pragma unroll
            for (int o = 4; o > 0; o >>= 1) {
                p += __shfl_down_sync(0xFFFFFFFFu, p, o);
                c += __shfl_down_sync(0xFFFFFFFFu, c, o);
                r += __shfl_down_sync(0xFFFFFFFFu, r, o);
            }
            if (lane == 0) {
                out[0] = r / (float)NTILE;                            // l_cm
                out[1] = (p + c) / (float)((size_t)NTILE * S2 * L2);  // l_c
                g_ticket = 0;                                         // rearm
                g_sync1  = 0;
            }
        }
    }
}

// ---------------------------------------------------------------------------
// Launch.  Inputs: [0] P f32, [1] index_r i32, [2] sw_abs i32, [3] lw_abs i32.
// ---------------------------------------------------------------------------
extern "C" void kernel_launch(void* const* d_in, const int* in_sizes, int n_in,
                              void* d_out, int out_size) {
    const float4* P4     = (const float4*)d_in[0];
    const float*  Pf     = (const float*)d_in[0];
    const int*    idxr   = (const int*)d_in[1];
    const int*    lw_abs = (const int*)d_in[3];
    float*        out    = (float*)d_out;

    k_all<<<NBLK, 256>>>(P4, Pf, idxr, lw_abs, out);
}